// round 17
// baseline (speedup 1.0000x reference)
#include <cuda_runtime.h>

#define HH    512
#define WW    512
#define HW    (HH * WW)
#define PAD   8
#define NKH   32
#define NKW   32
#define NK    1024
#define NC    33            // stride cells per dim (528/16)
#define BATCH 64
#define RPAD  36            // padded smem row (words): conflict-free LDS.128

// Zero-initialized device scratch (module load zeroes these; each launch
// restores them to zero -> graph-replay idempotent).
__device__ float    g_scratch[BATCH * NK];
__device__ unsigned g_ctr[BATCH * NK];

// Single fused kernel. One block per 16x16 stride cell (verified R6/R16
// geometry). Cell (Ri,Ci) covers padded pixels [16Ri,16Ri+16)x[16Ci,16Ci+16)
// feeding windows (Ri-i,Ci-j), i,j in {0,1}, at kernel offsets
// (dy+16i,dx+16j), q=i*2+j. Every output (b,n) receives EXACTLY 4
// contributions (cells r..r+1 x c..c+1 all exist).
//
// Mainloop: warp w owns batches 8w..8w+7; lane owns pixel-quads lane and
// lane+32. Weights staged once through 4KB smem, then registers. Depth-2
// pipelined x loads. Per batch: 32 FMA + 4 conflict-free STS.
// Completion protocol (replaces the init kernel): phase-2 thread adds its
// partial to g_scratch, fences, bumps g_ctr; the 4th arrival reads the full
// sum from L2, writes out = sum + bias exactly once, and re-zeroes
// scratch/ctr for the next launch.
__global__ __launch_bounds__(256, 4) void bslc_main(
    const float* __restrict__ x,       // (64,1,512,512)
    const float* __restrict__ weight,  // (NK,1024)
    const float* __restrict__ bias,    // (NK)
    float* __restrict__ out)           // (64,NK)
{
    __shared__ __align__(16) float4 w_s[2][4][32];        // 4KB staged weights
    __shared__ __align__(16) float  sred[8][8][4][RPAD];  // 36KB partials

    const int cell = blockIdx.x;
    const int Ri = cell / NC, Ci = cell % NC;
    const int tid  = threadIdx.x;
    const int lane = tid & 31;
    const int warp = tid >> 5;

    // Quadrant windows + validity (uniform across block, full 4-sided check)
    int nq[4]; bool vq[4];
#pragma unroll
    for (int q = 0; q < 4; q++) {
        const int r = Ri - (q >> 1), c = Ci - (q & 1);
        vq[q] = (r >= 0) && (r < NKH) && (c >= 0) && (c < NKW);
        nq[q] = vq[q] ? (r * NKW + c) : 0;
    }

    // Cooperative weight stage: warp ws -> (s = ws>>2, q = ws&3)
    {
        const int s  = warp >> 2;
        const int q  = warp & 3;
        const int dy = (lane >> 2) + 8 * s;
        const int dx = (lane & 3) << 2;
        float4 w = make_float4(0.f, 0.f, 0.f, 0.f);
        if (vq[q])
            w = *reinterpret_cast<const float4*>(
                    weight + nq[q] * 1024
                           + (dy + 16 * (q >> 1)) * 32
                           + (dx + 16 * (q & 1)));
        w_s[s][q][lane] = w;
    }
    __syncthreads();

    // Lane's weights to registers: 8 conflict-free LDS.128
    float4 wreg[2][4];
#pragma unroll
    for (int s = 0; s < 2; s++)
#pragma unroll
        for (int q = 0; q < 4; q++)
            wreg[s][q] = w_s[s][q][lane];

    // Lane's two pixel-quads (verbatim R6 indexing)
    bool ok[2]; int off[2];
#pragma unroll
    for (int s = 0; s < 2; s++) {
        const int dy = (lane >> 2) + 8 * s;
        const int dx = (lane & 3) << 2;
        const int uy = Ri * 16 + dy - PAD;
        const int ux = Ci * 16 + dx - PAD;
        ok[s]  = ((unsigned)uy < (unsigned)HH) &&
                 ((unsigned)ux <= (unsigned)(WW - 4));
        off[s] = uy * WW + ux;
    }

    const int b0 = warp * 8;
    const float* __restrict__ xb = x + (size_t)b0 * HW;

#define LDX(t, s) ( ok[s] ? *reinterpret_cast<const float4*>( \
                        xb + (size_t)(t) * HW + off[s])        \
                          : make_float4(0.f, 0.f, 0.f, 0.f) )

    // Depth-2 pipeline over the 8 batches (MLP = 4)
    float4 c0 = LDX(0, 0), c1 = LDX(0, 1);
    float4 n0 = LDX(1, 0), n1 = LDX(1, 1);

#pragma unroll
    for (int t = 0; t < 8; t++) {
        float4 p0, p1;
        if (t + 2 < 8) { p0 = LDX(t + 2, 0); p1 = LDX(t + 2, 1); }

#pragma unroll
        for (int q = 0; q < 4; q++) {
            float s;
            s = fmaf(c0.x, wreg[0][q].x,
                fmaf(c0.y, wreg[0][q].y,
                fmaf(c0.z, wreg[0][q].z, c0.w * wreg[0][q].w)));
            s = fmaf(c1.x, wreg[1][q].x,
                fmaf(c1.y, wreg[1][q].y,
                fmaf(c1.z, wreg[1][q].z, fmaf(c1.w, wreg[1][q].w, s))));
            sred[warp][t][q][lane] = s;        // conflict-free STS.32
        }

        c0 = n0; c1 = n1; n0 = p0; n1 = p1;
    }
#undef LDX

    __syncthreads();

    // Phase 2: thread -> (batch b = tid>>2, quadrant q = tid&3)
    {
        const int b = tid >> 2;                // 0..63
        const int q = tid & 3;
        const float4* row =
            reinterpret_cast<const float4*>(&sred[b >> 3][b & 7][q][0]);
        float4 s4 = make_float4(0.f, 0.f, 0.f, 0.f);
#pragma unroll
        for (int i = 0; i < 8; i++) {
            const float4 v = row[i];
            s4.x += v.x; s4.y += v.y; s4.z += v.z; s4.w += v.w;
        }
        const float s = (s4.x + s4.y) + (s4.z + s4.w);

        const int r = Ri - (q >> 1), c = Ci - (q & 1);
        if (r >= 0 && r < NKH && c >= 0 && c < NKW) {
            const int n    = r * NKW + c;
            const int idxo = b * NK + n;

            atomicAdd(&g_scratch[idxo], s);
            __threadfence();                       // publish before counting
            if (atomicAdd(&g_ctr[idxo], 1u) == 3u) {
                __threadfence();                   // see all 4 partials
                const float v = __ldcg(&g_scratch[idxo]);   // L2 read
                out[idxo] = v + __ldg(&bias[n]);
                __stcg(&g_scratch[idxo], 0.f);     // restore zero state
                g_ctr[idxo] = 0u;                  //   for the next replay
            }
        }
    }
}

extern "C" void kernel_launch(void* const* d_in, const int* in_sizes, int n_in,
                              void* d_out, int out_size)
{
    const float* x      = (const float*)d_in[0];   // (64,1,512,512) fp32
    const float* weight = (const float*)d_in[1];   // (1024,1024)    fp32
    const float* bias   = (const float*)d_in[2];   // (1024,)        fp32
    float*       out    = (float*)d_out;           // (64,32,32)     fp32

    bslc_main<<<NC * NC, 256>>>(x, weight, bias, out);   // single launch
}